// round 11
// baseline (speedup 1.0000x reference)
#include <cuda_runtime.h>
#include <cuda_fp16.h>
#include <stdint.h>

#define N_ROWS   262144
#define TILE_M   64
#define NTHREADS 256
#define SMEM_BYTES 102912

// fp16 weights: W2 [256][128] @0, W3 [128][256] @32768, W4 [512][128] @65536
__device__ __half g_Wh[131072];

__global__ void cvt_weights_kernel(const float* __restrict__ W2,
                                   const float* __restrict__ W3,
                                   const float* __restrict__ W4) {
    int i = blockIdx.x * blockDim.x + threadIdx.x;   // 65536 threads
    if (i < 32768) {
        g_Wh[i]         = __float2half_rn(W2[i]);
        g_Wh[32768 + i] = __float2half_rn(W3[i]);
    }
    g_Wh[65536 + i] = __float2half_rn(W4[i]);
}

__device__ __forceinline__ uint32_t smem_u32(const void* p) {
    return (uint32_t)__cvta_generic_to_shared(p);
}

__device__ __forceinline__ void ldmatrix_x4(uint32_t r[4], uint32_t addr) {
    asm volatile("ldmatrix.sync.aligned.m8n8.x4.shared.b16 {%0,%1,%2,%3}, [%4];\n"
                 : "=r"(r[0]), "=r"(r[1]), "=r"(r[2]), "=r"(r[3]) : "r"(addr));
}

__device__ __forceinline__ void mma16816(float c[4], const uint32_t a[4], uint32_t b0, uint32_t b1) {
    asm volatile("mma.sync.aligned.m16n8k16.row.col.f32.f16.f16.f32 "
                 "{%0,%1,%2,%3},{%4,%5,%6,%7},{%8,%9},{%0,%1,%2,%3};\n"
                 : "+f"(c[0]), "+f"(c[1]), "+f"(c[2]), "+f"(c[3])
                 : "r"(a[0]), "r"(a[1]), "r"(a[2]), "r"(a[3]), "r"(b0), "r"(b1));
}

__device__ __forceinline__ void cp_async16(uint32_t dst_smem, const void* src) {
    asm volatile("cp.async.cg.shared.global [%0], [%1], 16;\n" :: "r"(dst_smem), "l"(src));
}
__device__ __forceinline__ void cp_commit() { asm volatile("cp.async.commit_group;\n"); }
template <int n>
__device__ __forceinline__ void cp_wait() { asm volatile("cp.async.wait_group %0;\n" :: "n"(n)); }

// tanh-GELU in sigmoid form: gelu(x) = x * sigmoid(1.5957691x + 0.0713548x^3)
__device__ __forceinline__ float fast_gelu(float x) {
    float x3 = x * x * x;
    float z  = fmaf(0.0713548162726f, x3, 1.5957691216057308f * x);
    float e  = __expf(-z);
    return __fdividef(x, 1.0f + e);
}

__device__ __forceinline__ uint32_t pack_h2(float a, float b) {
    __half2 h = __floats2half2_rn(a, b);
    return *(uint32_t*)&h;
}

// swizzled byte offset for (row, col-halves) in region with row-bytes RB
__device__ __forceinline__ uint32_t swoff(int row, int col, int RB) {
    return (uint32_t)(row * RB + (((col >> 3) ^ (row & 7)) << 4) + ((col & 7) << 1));
}

// ---- 16KB weight chunk prefetch (swizzled), one commit group per chunk ----
__device__ __forceinline__ void pf64x128(const __half* src, uint32_t dst, int tid) {
#pragma unroll
    for (int k = 0; k < 4; ++k) {               // 64 rows x 128 halves, RB=256
        int i = tid + k * NTHREADS;
        int r = i >> 4, c = i & 15;
        cp_async16(dst + (uint32_t)(r * 256 + ((c ^ (r & 7)) << 4)), src + r * 128 + (c << 3));
    }
}
__device__ __forceinline__ void pf128x64(const __half* src, uint32_t dst, int tid) {
#pragma unroll
    for (int k = 0; k < 4; ++k) {               // 128 rows x 64 halves (src_ld=256), RB=128
        int i = tid + k * NTHREADS;
        int r = i >> 3, c = i & 7;
        cp_async16(dst + (uint32_t)(r * 128 + ((c ^ (r & 7)) << 4)), src + r * 256 + (c << 3));
    }
}
// chunks: 0-3 W2 N-split, 4-7 W3 K-split, 8-15 W4 N-split
__device__ __forceinline__ void prefetch_chunk(int ci, uint32_t dst, int tid) {
    if (ci < 4)       pf64x128(g_Wh + ci * 8192, dst, tid);
    else if (ci < 8)  pf128x64(g_Wh + 32768 + (ci - 4) * 64, dst, tid);
    else              pf64x128(g_Wh + 65536 + (ci - 8) * 8192, dst, tid);
    cp_commit();
}

// SMEM: ring buf0/1/2 @0/16384/32768 (16KB each); hA @49152 (16KB, h1->h3);
//       hB @65536 (32KB, h2); sW1 @98304; sB1 @100352; sB2 @100864; sB3 @101888;
//       sTok @102400; sPad @102656  => 102912
#define oHA 49152
#define oHB 65536

__global__ __launch_bounds__(NTHREADS, 2)
void embedder_kernel(const float* __restrict__ joint_info,
                     const int* __restrict__ joint_token,
                     const float* __restrict__ emb,
                     const float* __restrict__ W1, const float* __restrict__ b1,
                     const float* __restrict__ b2, const float* __restrict__ b3,
                     float* __restrict__ out) {
    extern __shared__ char smem[];
    const uint32_t S = smem_u32(smem);
    float* sW1 = (float*)(smem + 98304);
    float* sB1 = (float*)(smem + 100352);
    float* sB2 = (float*)(smem + 100864);
    float* sB3 = (float*)(smem + 101888);
    int*   sTok = (int*)(smem + 102400);
    int*   sPad = (int*)(smem + 102656);

    int tid  = threadIdx.x;
    int lane = tid & 31, warp = tid >> 5;
    int wm = warp >> 2, wn = warp & 3;           // 2M x 4N warp grid
    int R0 = blockIdx.x * TILE_M;

    // ---- prefetch chunks 0,1 ----
    prefetch_chunk(0, S, tid);
    prefetch_chunk(1, S + 16384, tid);

    // ---- small data ----
    if (tid < 64) {
        float4 xx = ((const float4*)joint_info)[R0 + tid];
        sPad[tid] = (xx.x == 0.0f && xx.y == 0.0f && xx.z == 0.0f && xx.w == 0.0f) ? 1 : 0;
        sTok[tid] = joint_token[R0 + tid];
    }
    if (tid < 128) {
        sB1[tid] = b1[tid];
        sB3[tid] = b3[tid];
    }
    sB2[tid] = b2[tid];
    ((float2*)sW1)[tid] = ((const float2*)W1)[tid];   // 512 floats
    __syncthreads();

    // ---- layer 1 (K=4, fp32 exact): 4 threads/row, 32 cols each -> h1 @hA (RB 256) ----
    {
        int row = tid >> 2, q = tid & 3;
        float4 x = ((const float4*)joint_info)[R0 + row];
        int r7 = row & 7;
#pragma unroll
        for (int cc = 0; cc < 4; ++cc) {
            int c16 = q * 4 + cc;
            uint32_t v[4];
#pragma unroll
            for (int j = 0; j < 4; ++j) {
                int c = c16 * 8 + j * 2;
                float4 wa = *(const float4*)&sW1[c * 4];
                float4 wb = *(const float4*)&sW1[(c + 1) * 4];
                float y0 = fmaf(x.x, wa.x, fmaf(x.y, wa.y, fmaf(x.z, wa.z, fmaf(x.w, wa.w, sB1[c]))));
                float y1 = fmaf(x.x, wb.x, fmaf(x.y, wb.y, fmaf(x.z, wb.z, fmaf(x.w, wb.w, sB1[c + 1]))));
                v[j] = pack_h2(fast_gelu(y0), fast_gelu(y1));
            }
            *(uint4*)(smem + oHA + row * 256 + ((c16 ^ r7) << 4)) = *(uint4*)v;
        }
    }

    // per-lane fragment coords
    int g = lane >> 2, t = lane & 3;
    int ri = lane & 7, mi = lane >> 3, sel = mi >> 1;
    int wrow = ri + ((mi & 1) << 3);

    // ========== layer 2: h1[64x128] @ W2 chunks [64x128] -> h2 @hB (RB 512) ==========
#pragma unroll
    for (int ci = 0; ci < 4; ++ci) {
        cp_wait<1>();
        __syncthreads();
        prefetch_chunk(ci + 2, S + ((ci + 2) % 3) * 16384, tid);
        const uint32_t bb = S + (ci % 3) * 16384;

        float acc[2][8];
#pragma unroll
        for (int s = 0; s < 2; ++s)
#pragma unroll
            for (int q = 0; q < 8; ++q) acc[s][q] = 0.0f;

        uint32_t a0 = S + oHA + (uint32_t)((32 * wm + wrow) * 256);
        uint32_t a1 = a0 + 16 * 256;
        uint32_t bB = bb + (uint32_t)((16 * wn + wrow) * 256);
#pragma unroll
        for (int kt = 0; kt < 8; ++kt) {
            uint32_t sw = (uint32_t)(((2 * kt + sel) ^ ri) << 4);
            uint32_t A0[4], A1[4], B[4];
            ldmatrix_x4(A0, a0 + sw);
            ldmatrix_x4(A1, a1 + sw);
            ldmatrix_x4(B, bB + sw);
            mma16816(acc[0] + 0, A0, B[0], B[2]);
            mma16816(acc[0] + 4, A0, B[1], B[3]);
            mma16816(acc[1] + 0, A1, B[0], B[2]);
            mma16816(acc[1] + 4, A1, B[1], B[3]);
        }

        int c0 = 64 * ci + 16 * wn + 2 * t, c1 = c0 + 8;
        float b0v = sB2[c0], b1v = sB2[c0 + 1];
        float b2v = sB2[c1], b3v = sB2[c1 + 1];
#pragma unroll
        for (int s = 0; s < 2; ++s) {
            int rl = 32 * wm + 16 * s + g, rh = rl + 8;
            const float* a = acc[s];
            *(uint32_t*)(smem + oHB + swoff(rl, c0, 512)) =
                pack_h2(fast_gelu(a[0] + b0v), fast_gelu(a[1] + b1v));
            *(uint32_t*)(smem + oHB + swoff(rh, c0, 512)) =
                pack_h2(fast_gelu(a[2] + b0v), fast_gelu(a[3] + b1v));
            *(uint32_t*)(smem + oHB + swoff(rl, c1, 512)) =
                pack_h2(fast_gelu(a[4] + b2v), fast_gelu(a[5] + b3v));
            *(uint32_t*)(smem + oHB + swoff(rh, c1, 512)) =
                pack_h2(fast_gelu(a[6] + b2v), fast_gelu(a[7] + b3v));
        }
    }

    // ========== layer 3: h2[64x256] @ W3 K-chunks [128x64] -> h3 @hA (RB 256) ==========
    {
        float acc[2][2][8];
#pragma unroll
        for (int s = 0; s < 2; ++s)
#pragma unroll
            for (int n = 0; n < 2; ++n)
#pragma unroll
                for (int q = 0; q < 8; ++q) acc[s][n][q] = 0.0f;

#pragma unroll
        for (int ci = 4; ci < 8; ++ci) {
            cp_wait<1>();
            __syncthreads();
            prefetch_chunk(ci + 2, S + ((ci + 2) % 3) * 16384, tid);
            const uint32_t bb = S + (ci % 3) * 16384;
            int kc = ci - 4;

            uint32_t a0 = S + oHB + (uint32_t)((32 * wm + wrow) * 512);
            uint32_t a1 = a0 + 16 * 512;
            uint32_t bB0 = bb + (uint32_t)((32 * wn + wrow) * 128);
            uint32_t bB1 = bB0 + 16 * 128;
#pragma unroll
            for (int ktl = 0; ktl < 4; ++ktl) {
                uint32_t swA = (uint32_t)(((8 * kc + 2 * ktl + sel) ^ ri) << 4);
                uint32_t swB = (uint32_t)(((2 * ktl + sel) ^ ri) << 4);
                uint32_t A0[4], A1[4], B0[4], B1[4];
                ldmatrix_x4(A0, a0 + swA);
                ldmatrix_x4(A1, a1 + swA);
                ldmatrix_x4(B0, bB0 + swB);
                ldmatrix_x4(B1, bB1 + swB);
                mma16816(acc[0][0] + 0, A0, B0[0], B0[2]);
                mma16816(acc[0][0] + 4, A0, B0[1], B0[3]);
                mma16816(acc[0][1] + 0, A0, B1[0], B1[2]);
                mma16816(acc[0][1] + 4, A0, B1[1], B1[3]);
                mma16816(acc[1][0] + 0, A1, B0[0], B0[2]);
                mma16816(acc[1][0] + 4, A1, B0[1], B0[3]);
                mma16816(acc[1][1] + 0, A1, B1[0], B1[2]);
                mma16816(acc[1][1] + 4, A1, B1[1], B1[3]);
            }
        }

        // epilogue -> h3 @hA (h1 dead)
#pragma unroll
        for (int n = 0; n < 2; ++n) {
            int c0 = 32 * wn + 16 * n + 2 * t, c1 = c0 + 8;
            float b0v = sB3[c0], b1v = sB3[c0 + 1];
            float b2v = sB3[c1], b3v = sB3[c1 + 1];
#pragma unroll
            for (int s = 0; s < 2; ++s) {
                int rl = 32 * wm + 16 * s + g, rh = rl + 8;
                const float* a = acc[s][n];
                *(uint32_t*)(smem + oHA + swoff(rl, c0, 256)) =
                    pack_h2(fast_gelu(a[0] + b0v), fast_gelu(a[1] + b1v));
                *(uint32_t*)(smem + oHA + swoff(rh, c0, 256)) =
                    pack_h2(fast_gelu(a[2] + b0v), fast_gelu(a[3] + b1v));
                *(uint32_t*)(smem + oHA + swoff(rl, c1, 256)) =
                    pack_h2(fast_gelu(a[4] + b2v), fast_gelu(a[5] + b3v));
                *(uint32_t*)(smem + oHA + swoff(rh, c1, 256)) =
                    pack_h2(fast_gelu(a[6] + b2v), fast_gelu(a[7] + b3v));
            }
        }
    }

    // ========== layer 4: h3[64x128] @ W4 chunks [64x128] -> out + emb/pad ==========
#pragma unroll
    for (int ci = 8; ci < 16; ++ci) {
        if (ci == 15) { cp_wait<0>(); } else { cp_wait<1>(); }
        __syncthreads();
        if (ci + 2 < 16) prefetch_chunk(ci + 2, S + ((ci + 2) % 3) * 16384, tid);
        const uint32_t bb = S + (ci % 3) * 16384;

        float acc[2][8];
#pragma unroll
        for (int s = 0; s < 2; ++s)
#pragma unroll
            for (int q = 0; q < 8; ++q) acc[s][q] = 0.0f;

        uint32_t a0 = S + oHA + (uint32_t)((32 * wm + wrow) * 256);
        uint32_t a1 = a0 + 16 * 256;
        uint32_t bB = bb + (uint32_t)((16 * wn + wrow) * 256);
#pragma unroll
        for (int kt = 0; kt < 8; ++kt) {
            uint32_t sw = (uint32_t)(((2 * kt + sel) ^ ri) << 4);
            uint32_t A0[4], A1[4], B[4];
            ldmatrix_x4(A0, a0 + sw);
            ldmatrix_x4(A1, a1 + sw);
            ldmatrix_x4(B, bB + sw);
            mma16816(acc[0] + 0, A0, B[0], B[2]);
            mma16816(acc[0] + 4, A0, B[1], B[3]);
            mma16816(acc[1] + 0, A1, B[0], B[2]);
            mma16816(acc[1] + 4, A1, B[1], B[3]);
        }

        int cc0 = 64 * (ci - 8) + 16 * wn + 2 * t;
        int cc1 = cc0 + 8;
#pragma unroll
        for (int s = 0; s < 2; ++s) {
            int rl = 32 * wm + 16 * s + g, rh = rl + 8;
            int pl = sPad[rl], ph = sPad[rh];
            const float* el = emb + (pl ? 0 : sTok[rl]) * 512;
            const float* eh = emb + (ph ? 0 : sTok[rh]) * 512;
            float* ol = out + (size_t)(R0 + rl) * 512;
            float* oh = out + (size_t)(R0 + rh) * 512;
            const float* a = acc[s];
            float2 e, o;
            e = *(const float2*)(el + cc0);
            o.x = pl ? e.x : (a[0] + e.x);  o.y = pl ? e.y : (a[1] + e.y);
            *(float2*)(ol + cc0) = o;
            e = *(const float2*)(eh + cc0);
            o.x = ph ? e.x : (a[2] + e.x);  o.y = ph ? e.y : (a[3] + e.y);
            *(float2*)(oh + cc0) = o;
            e = *(const float2*)(el + cc1);
            o.x = pl ? e.x : (a[4] + e.x);  o.y = pl ? e.y : (a[5] + e.y);
            *(float2*)(ol + cc1) = o;
            e = *(const float2*)(eh + cc1);
            o.x = ph ? e.x : (a[6] + e.x);  o.y = ph ? e.y : (a[7] + e.y);
            *(float2*)(oh + cc1) = o;
        }
    }
}

extern "C" void kernel_launch(void* const* d_in, const int* in_sizes, int n_in,
                              void* d_out, int out_size) {
    const float* joint_info  = (const float*)d_in[0];
    const int*   joint_token = (const int*)d_in[1];
    const float* emb         = (const float*)d_in[2];
    const float* W1          = (const float*)d_in[3];
    const float* b1          = (const float*)d_in[4];
    const float* W2          = (const float*)d_in[5];
    const float* b2          = (const float*)d_in[6];
    const float* W3          = (const float*)d_in[7];
    const float* b3          = (const float*)d_in[8];
    const float* W4          = (const float*)d_in[9];

    cvt_weights_kernel<<<256, 256>>>(W2, W3, W4);

    cudaFuncSetAttribute(embedder_kernel,
                         cudaFuncAttributeMaxDynamicSharedMemorySize, SMEM_BYTES);
    embedder_kernel<<<N_ROWS / TILE_M, NTHREADS, SMEM_BYTES>>>(
        joint_info, joint_token, emb, W1, b1, b2, b3, (float*)d_out);
}

// round 15
// speedup vs baseline: 1.0397x; 1.0397x over previous
#include <cuda_runtime.h>
#include <cuda_fp16.h>
#include <stdint.h>

#define N_ROWS   262144
#define TILE_M   128
#define NTHREADS 256
#define SMEM_BYTES 56320

// fp16 weights: W2 [256][128] @0, W3 [128][256] @32768, W4 [512][128] @65536
__device__ __half g_Wh[131072];

__global__ void cvt_weights_kernel(const float* __restrict__ W2,
                                   const float* __restrict__ W3,
                                   const float* __restrict__ W4) {
    int i = blockIdx.x * blockDim.x + threadIdx.x;   // 65536 threads
    if (i < 32768) {
        g_Wh[i]         = __float2half_rn(W2[i]);
        g_Wh[32768 + i] = __float2half_rn(W3[i]);
    }
    g_Wh[65536 + i] = __float2half_rn(W4[i]);
}

__device__ __forceinline__ uint32_t smem_u32(const void* p) {
    return (uint32_t)__cvta_generic_to_shared(p);
}

__device__ __forceinline__ void ldmatrix_x4(uint32_t r[4], uint32_t addr) {
    asm volatile("ldmatrix.sync.aligned.m8n8.x4.shared.b16 {%0,%1,%2,%3}, [%4];\n"
                 : "=r"(r[0]), "=r"(r[1]), "=r"(r[2]), "=r"(r[3]) : "r"(addr));
}

__device__ __forceinline__ void mma16816(float c[4], const uint32_t a[4], uint32_t b0, uint32_t b1) {
    asm volatile("mma.sync.aligned.m16n8k16.row.col.f32.f16.f16.f32 "
                 "{%0,%1,%2,%3},{%4,%5,%6,%7},{%8,%9},{%0,%1,%2,%3};\n"
                 : "+f"(c[0]), "+f"(c[1]), "+f"(c[2]), "+f"(c[3])
                 : "r"(a[0]), "r"(a[1]), "r"(a[2]), "r"(a[3]), "r"(b0), "r"(b1));
}

__device__ __forceinline__ void cp_async16(uint32_t dst_smem, const void* src) {
    asm volatile("cp.async.cg.shared.global [%0], [%1], 16;\n" :: "r"(dst_smem), "l"(src));
}
__device__ __forceinline__ void cp_commit() { asm volatile("cp.async.commit_group;\n"); }
template <int n>
__device__ __forceinline__ void cp_wait() { asm volatile("cp.async.wait_group %0;\n" :: "n"(n)); }

// tanh-GELU in sigmoid form: gelu(x) = x * sigmoid(1.5957691x + 0.0713548x^3)
__device__ __forceinline__ float fast_gelu(float x) {
    float x3 = x * x * x;
    float z  = fmaf(0.0713548162726f, x3, 1.5957691216057308f * x);
    float e  = __expf(-z);
    return __fdividef(x, 1.0f + e);
}

__device__ __forceinline__ uint32_t pack_h2(float a, float b) {
    __half2 h = __floats2half2_rn(a, b);
    return *(uint32_t*)&h;
}

// ---- 16KB N-split weight chunks, swizzled ----
// ci 0-3 : W2 rows [64ci, 64ci+64) x 128K      -> [64][128],  RB=256
// ci 4-7 : W3 rows [32(ci-4), +32) x 256K      -> [32][256],  RB=512
// ci 8-15: W4 rows [64(ci-8), +64) x 128K      -> [64][128],  RB=256
__device__ __forceinline__ void prefetch_chunk(int ci, uint32_t dst, int tid) {
    if (ci < 8 ? (ci < 4) : true) {
        const __half* src = (ci < 4) ? (g_Wh + ci * 8192) : (g_Wh + 65536 + (ci - 8) * 8192);
#pragma unroll
        for (int k = 0; k < 4; ++k) {
            int i = tid + k * NTHREADS;
            int r = i >> 4, c = i & 15;
            cp_async16(dst + (uint32_t)(r * 256 + ((c ^ (r & 7)) << 4)), src + r * 128 + (c << 3));
        }
    } else {
        const __half* src = g_Wh + 32768 + (ci - 4) * 8192;
#pragma unroll
        for (int k = 0; k < 4; ++k) {
            int i = tid + k * NTHREADS;
            int r = i >> 5, c = i & 31;
            cp_async16(dst + (uint32_t)(r * 512 + ((c ^ (r & 7)) << 4)), src + r * 256 + (c << 3));
        }
    }
    cp_commit();
}

// SMEM: ring 3x16384 @0; sX @49152 (2048); sW1 @51200 (2048); sB1 @53248 (512);
//       sB2 @53760 (1024); sB3 @54784 (512); sTok @55296 (512); sPad @55808 (512) => 56320
__global__ __launch_bounds__(NTHREADS, 2)
void embedder_kernel(const float* __restrict__ joint_info,
                     const int* __restrict__ joint_token,
                     const float* __restrict__ emb,
                     const float* __restrict__ W1, const float* __restrict__ b1,
                     const float* __restrict__ b2, const float* __restrict__ b3,
                     float* __restrict__ out) {
    extern __shared__ char smem[];
    const uint32_t S = smem_u32(smem);
    float4* sX  = (float4*)(smem + 49152);
    float*  sW1 = (float*)(smem + 51200);
    float*  sB1 = (float*)(smem + 53248);
    float*  sB2 = (float*)(smem + 53760);
    float*  sB3 = (float*)(smem + 54784);
    int*    sTok = (int*)(smem + 55296);
    int*    sPad = (int*)(smem + 55808);

    int tid  = threadIdx.x;
    int lane = tid & 31, warp = tid >> 5;
    int R0   = blockIdx.x * TILE_M;

    // ---- prefetch chunks 0,1 ----
    prefetch_chunk(0, S, tid);
    prefetch_chunk(1, S + 16384, tid);

    // ---- small data ----
    if (tid < 128) {
        float4 x = ((const float4*)joint_info)[R0 + tid];
        sX[tid]   = x;
        sTok[tid] = joint_token[R0 + tid];
        sPad[tid] = (x.x == 0.0f && x.y == 0.0f && x.z == 0.0f && x.w == 0.0f) ? 1 : 0;
        sB1[tid]  = b1[tid];
        sB3[tid]  = b3[tid];
    }
    sB2[tid] = b2[tid];
    ((float2*)sW1)[tid] = ((const float2*)W1)[tid];   // 512 floats of W1
    __syncthreads();

    // per-lane fragment coords
    int g = lane >> 2, t = lane & 3;
    int ri = lane & 7, mi = lane >> 3, sel = mi >> 1;
    int wrow = ri + ((mi & 1) << 3);
    int r0 = warp * 16;

    // ---- layer 1 (K=4) scalar fp32 -> h1 A-fragments (16 rows x 128 cols per warp) ----
    uint32_t h1A[8][4];
    {
        float4 xa = sX[r0 + g];
        float4 xb = sX[r0 + g + 8];
#pragma unroll
        for (int kt = 0; kt < 8; ++kt)
#pragma unroll
            for (int j = 0; j < 2; ++j) {
                int c0 = kt * 16 + j * 8 + t * 2;
                float4 w0 = *(const float4*)&sW1[c0 * 4];
                float4 w1 = *(const float4*)&sW1[(c0 + 1) * 4];
                float bb0 = sB1[c0], bb1 = sB1[c0 + 1];
                float ya0 = fmaf(xa.x, w0.x, fmaf(xa.y, w0.y, fmaf(xa.z, w0.z, fmaf(xa.w, w0.w, bb0))));
                float ya1 = fmaf(xa.x, w1.x, fmaf(xa.y, w1.y, fmaf(xa.z, w1.z, fmaf(xa.w, w1.w, bb1))));
                float yb0 = fmaf(xb.x, w0.x, fmaf(xb.y, w0.y, fmaf(xb.z, w0.z, fmaf(xb.w, w0.w, bb0))));
                float yb1 = fmaf(xb.x, w1.x, fmaf(xb.y, w1.y, fmaf(xb.z, w1.z, fmaf(xb.w, w1.w, bb1))));
                h1A[kt][2 * j + 0] = pack_h2(fast_gelu(ya0), fast_gelu(ya1));
                h1A[kt][2 * j + 1] = pack_h2(fast_gelu(yb0), fast_gelu(yb1));
            }
    }

    // ================= layer 2: h1[16x128] @ W2 (4 N-chunks of 64) =================
    uint32_t h2A[16][4];
#pragma unroll
    for (int ci = 0; ci < 4; ++ci) {
        cp_wait<1>();
        __syncthreads();
        prefetch_chunk(ci + 2, S + (uint32_t)(((ci + 2) % 3) * 16384), tid);
        const uint32_t bb = S + (uint32_t)((ci % 3) * 16384);
#pragma unroll
        for (int j = 0; j < 4; ++j) {
            uint32_t bRow = bb + (uint32_t)((16 * j + wrow) * 256);
            float c[8] = {0, 0, 0, 0, 0, 0, 0, 0};
#pragma unroll
            for (int kt = 0; kt < 8; ++kt) {
                uint32_t B[4];
                ldmatrix_x4(B, bRow + (uint32_t)(((2 * kt + sel) ^ ri) << 4));
                mma16816(c + 0, h1A[kt], B[0], B[2]);
                mma16816(c + 4, h1A[kt], B[1], B[3]);
            }
            int ng = 4 * ci + j;
            int nb = ng * 16;
            float b0 = sB2[nb + 2 * t], b1v = sB2[nb + 2 * t + 1];
            float b2v = sB2[nb + 8 + 2 * t], b3v = sB2[nb + 9 + 2 * t];
            h2A[ng][0] = pack_h2(fast_gelu(c[0] + b0), fast_gelu(c[1] + b1v));
            h2A[ng][1] = pack_h2(fast_gelu(c[2] + b0), fast_gelu(c[3] + b1v));
            h2A[ng][2] = pack_h2(fast_gelu(c[4] + b2v), fast_gelu(c[5] + b3v));
            h2A[ng][3] = pack_h2(fast_gelu(c[6] + b2v), fast_gelu(c[7] + b3v));
        }
    }

    // ================= layer 3: h2[16x256] @ W3 (4 N-chunks of 32) =================
    uint32_t h3A[8][4];
#pragma unroll
    for (int ci = 4; ci < 8; ++ci) {
        cp_wait<1>();
        __syncthreads();
        prefetch_chunk(ci + 2, S + (uint32_t)(((ci + 2) % 3) * 16384), tid);
        const uint32_t bb = S + (uint32_t)((ci % 3) * 16384);
#pragma unroll
        for (int j = 0; j < 2; ++j) {
            uint32_t bRow = bb + (uint32_t)((16 * j + wrow) * 512);
            float c[8] = {0, 0, 0, 0, 0, 0, 0, 0};
#pragma unroll
            for (int kt = 0; kt < 16; ++kt) {
                uint32_t B[4];
                ldmatrix_x4(B, bRow + (uint32_t)(((2 * kt + sel) ^ ri) << 4));
                mma16816(c + 0, h2A[kt], B[0], B[2]);
                mma16816(c + 4, h2A[kt], B[1], B[3]);
            }
            int ng = 2 * (ci - 4) + j;
            int nb = ng * 16;
            float b0 = sB3[nb + 2 * t], b1v = sB3[nb + 2 * t + 1];
            float b2v = sB3[nb + 8 + 2 * t], b3v = sB3[nb + 9 + 2 * t];
            h3A[ng][0] = pack_h2(fast_gelu(c[0] + b0), fast_gelu(c[1] + b1v));
            h3A[ng][1] = pack_h2(fast_gelu(c[2] + b0), fast_gelu(c[3] + b1v));
            h3A[ng][2] = pack_h2(fast_gelu(c[4] + b2v), fast_gelu(c[5] + b3v));
            h3A[ng][3] = pack_h2(fast_gelu(c[6] + b2v), fast_gelu(c[7] + b3v));
        }
    }

    // ---- epilogue row constants ----
    int pa = sPad[r0 + g], pb = sPad[r0 + g + 8];
    int ta = pa ? 0 : sTok[r0 + g];
    int tb = pb ? 0 : sTok[r0 + g + 8];
    const float* ea = emb + ta * 512;
    const float* eb = emb + tb * 512;
    float* outa = out + (size_t)(R0 + r0 + g) * 512;
    float* outb = out + (size_t)(R0 + r0 + g + 8) * 512;

    // ================= layer 4: h3[16x128] @ W4 (8 N-chunks of 64) + emb/pad =========
#pragma unroll
    for (int ci = 8; ci < 16; ++ci) {
        if (ci == 15) { cp_wait<0>(); } else { cp_wait<1>(); }
        __syncthreads();
        if (ci + 2 < 16) prefetch_chunk(ci + 2, S + (uint32_t)(((ci + 2) % 3) * 16384), tid);
        const uint32_t bb = S + (uint32_t)((ci % 3) * 16384);
#pragma unroll
        for (int j = 0; j < 4; ++j) {
            uint32_t bRow = bb + (uint32_t)((16 * j + wrow) * 256);
            float c[8] = {0, 0, 0, 0, 0, 0, 0, 0};
#pragma unroll
            for (int kt = 0; kt < 8; ++kt) {
                uint32_t B[4];
                ldmatrix_x4(B, bRow + (uint32_t)(((2 * kt + sel) ^ ri) << 4));
                mma16816(c + 0, h3A[kt], B[0], B[2]);
                mma16816(c + 4, h3A[kt], B[1], B[3]);
            }
            int cc0 = 64 * (ci - 8) + 16 * j + 2 * t;
            int cc1 = cc0 + 8;
            float2 e, o;
            e = *(const float2*)(ea + cc0);
            o.x = pa ? e.x : (c[0] + e.x);  o.y = pa ? e.y : (c[1] + e.y);
            *(float2*)(outa + cc0) = o;
            e = *(const float2*)(eb + cc0);
            o.x = pb ? e.x : (c[2] + e.x);  o.y = pb ? e.y : (c[3] + e.y);
            *(float2*)(outb + cc0) = o;
            e = *(const float2*)(ea + cc1);
            o.x = pa ? e.x : (c[4] + e.x);  o.y = pa ? e.y : (c[5] + e.y);
            *(float2*)(outa + cc1) = o;
            e = *(const float2*)(eb + cc1);
            o.x = pb ? e.x : (c[6] + e.x);  o.y = pb ? e.y : (c[7] + e.y);
            *(float2*)(outb + cc1) = o;
        }
    }
}

extern "C" void kernel_launch(void* const* d_in, const int* in_sizes, int n_in,
                              void* d_out, int out_size) {
    const float* joint_info  = (const float*)d_in[0];
    const int*   joint_token = (const int*)d_in[1];
    const float* emb         = (const float*)d_in[2];
    const float* W1          = (const float*)d_in[3];
    const float* b1          = (const float*)d_in[4];
    const float* W2          = (const float*)d_in[5];
    const float* b2          = (const float*)d_in[6];
    const float* W3          = (const float*)d_in[7];
    const float* b3          = (const float*)d_in[8];
    const float* W4          = (const float*)d_in[9];

    cvt_weights_kernel<<<256, 256>>>(W2, W3, W4);

    cudaFuncSetAttribute(embedder_kernel,
                         cudaFuncAttributeMaxDynamicSharedMemorySize, SMEM_BYTES);
    embedder_kernel<<<N_ROWS / TILE_M, NTHREADS, SMEM_BYTES>>>(
        joint_info, joint_token, emb, W1, b1, b2, b3, (float*)d_out);
}

// round 16
// speedup vs baseline: 1.2967x; 1.2472x over previous
#include <cuda_runtime.h>
#include <cuda_fp16.h>
#include <stdint.h>

#define N_ROWS   262144
#define TILE_M   128
#define NTHREADS 256
#define SMEM_BYTES 56320

// fp16 weights: W2 [256][128] @0, W3 [128][256] @32768, W4 [512][128] @65536
__device__ __half g_Wh[131072];

__global__ void cvt_weights_kernel(const float* __restrict__ W2,
                                   const float* __restrict__ W3,
                                   const float* __restrict__ W4) {
    int i = blockIdx.x * blockDim.x + threadIdx.x;   // 65536 threads
    if (i < 32768) {
        g_Wh[i]         = __float2half_rn(W2[i]);
        g_Wh[32768 + i] = __float2half_rn(W3[i]);
    }
    g_Wh[65536 + i] = __float2half_rn(W4[i]);
}

__device__ __forceinline__ uint32_t smem_u32(const void* p) {
    return (uint32_t)__cvta_generic_to_shared(p);
}

__device__ __forceinline__ void ldmatrix_x4(uint32_t r[4], uint32_t addr) {
    asm volatile("ldmatrix.sync.aligned.m8n8.x4.shared.b16 {%0,%1,%2,%3}, [%4];\n"
                 : "=r"(r[0]), "=r"(r[1]), "=r"(r[2]), "=r"(r[3]) : "r"(addr));
}

__device__ __forceinline__ void mma16816(float c[4], const uint32_t a[4], uint32_t b0, uint32_t b1) {
    asm volatile("mma.sync.aligned.m16n8k16.row.col.f32.f16.f16.f32 "
                 "{%0,%1,%2,%3},{%4,%5,%6,%7},{%8,%9},{%0,%1,%2,%3};\n"
                 : "+f"(c[0]), "+f"(c[1]), "+f"(c[2]), "+f"(c[3])
                 : "r"(a[0]), "r"(a[1]), "r"(a[2]), "r"(a[3]), "r"(b0), "r"(b1));
}

__device__ __forceinline__ void cp_async16(uint32_t dst_smem, const void* src) {
    asm volatile("cp.async.cg.shared.global [%0], [%1], 16;\n" :: "r"(dst_smem), "l"(src));
}
__device__ __forceinline__ void cp_commit() { asm volatile("cp.async.commit_group;\n"); }
template <int n>
__device__ __forceinline__ void cp_wait() { asm volatile("cp.async.wait_group %0;\n" :: "n"(n)); }

// tanh-GELU via MUFU.TANH: gelu(x) = 0.5x * (1 + tanh(0.79788456x + 0.03567741x^3))
// Same function as the previous sigmoid form, 6 instrs + 1 MUFU instead of ~10 + 2 MUFU.
__device__ __forceinline__ float fast_gelu(float x) {
    float x2 = x * x;
    float t  = fmaf(0.0356774081f, x2, 0.7978845608f);
    float z  = x * t;
    float th;
    asm("tanh.approx.f32 %0, %1;" : "=f"(th) : "f"(z));
    float hx = 0.5f * x;
    return fmaf(hx, th, hx);
}

__device__ __forceinline__ uint32_t pack_h2(float a, float b) {
    __half2 h = __floats2half2_rn(a, b);
    return *(uint32_t*)&h;
}

// ---- 16KB N-split weight chunks, swizzled ----
// ci 0-3 : W2 rows [64ci, 64ci+64) x 128K      -> [64][128],  RB=256
// ci 4-7 : W3 rows [32(ci-4), +32) x 256K      -> [32][256],  RB=512
// ci 8-15: W4 rows [64(ci-8), +64) x 128K      -> [64][128],  RB=256
__device__ __forceinline__ void prefetch_chunk(int ci, uint32_t dst, int tid) {
    if (ci < 8 ? (ci < 4) : true) {
        const __half* src = (ci < 4) ? (g_Wh + ci * 8192) : (g_Wh + 65536 + (ci - 8) * 8192);
#pragma unroll
        for (int k = 0; k < 4; ++k) {
            int i = tid + k * NTHREADS;
            int r = i >> 4, c = i & 15;
            cp_async16(dst + (uint32_t)(r * 256 + ((c ^ (r & 7)) << 4)), src + r * 128 + (c << 3));
        }
    } else {
        const __half* src = g_Wh + 32768 + (ci - 4) * 8192;
#pragma unroll
        for (int k = 0; k < 4; ++k) {
            int i = tid + k * NTHREADS;
            int r = i >> 5, c = i & 31;
            cp_async16(dst + (uint32_t)(r * 512 + ((c ^ (r & 7)) << 4)), src + r * 256 + (c << 3));
        }
    }
    cp_commit();
}

// SMEM: ring 3x16384 @0; sX @49152 (2048); sW1 @51200 (2048); sB1 @53248 (512);
//       sB2 @53760 (1024); sB3 @54784 (512); sTok @55296 (512); sPad @55808 (512) => 56320
__global__ __launch_bounds__(NTHREADS, 2)
void embedder_kernel(const float* __restrict__ joint_info,
                     const int* __restrict__ joint_token,
                     const float* __restrict__ emb,
                     const float* __restrict__ W1, const float* __restrict__ b1,
                     const float* __restrict__ b2, const float* __restrict__ b3,
                     float* __restrict__ out) {
    extern __shared__ char smem[];
    const uint32_t S = smem_u32(smem);
    float4* sX  = (float4*)(smem + 49152);
    float*  sW1 = (float*)(smem + 51200);
    float*  sB1 = (float*)(smem + 53248);
    float*  sB2 = (float*)(smem + 53760);
    float*  sB3 = (float*)(smem + 54784);
    int*    sTok = (int*)(smem + 55296);
    int*    sPad = (int*)(smem + 55808);

    int tid  = threadIdx.x;
    int lane = tid & 31, warp = tid >> 5;
    int R0   = blockIdx.x * TILE_M;

    // ---- prefetch chunks 0,1 ----
    prefetch_chunk(0, S, tid);
    prefetch_chunk(1, S + 16384, tid);

    // ---- small data ----
    if (tid < 128) {
        float4 x = ((const float4*)joint_info)[R0 + tid];
        sX[tid]   = x;
        sTok[tid] = joint_token[R0 + tid];
        sPad[tid] = (x.x == 0.0f && x.y == 0.0f && x.z == 0.0f && x.w == 0.0f) ? 1 : 0;
        sB1[tid]  = b1[tid];
        sB3[tid]  = b3[tid];
    }
    sB2[tid] = b2[tid];
    ((float2*)sW1)[tid] = ((const float2*)W1)[tid];   // 512 floats of W1
    __syncthreads();

    // per-lane fragment coords
    int g = lane >> 2, t = lane & 3;
    int ri = lane & 7, mi = lane >> 3, sel = mi >> 1;
    int wrow = ri + ((mi & 1) << 3);
    int r0 = warp * 16;

    // ---- layer 1 (K=4) scalar fp32 -> h1 A-fragments (16 rows x 128 cols per warp) ----
    uint32_t h1A[8][4];
    {
        float4 xa = sX[r0 + g];
        float4 xb = sX[r0 + g + 8];
#pragma unroll
        for (int kt = 0; kt < 8; ++kt)
#pragma unroll
            for (int j = 0; j < 2; ++j) {
                int c0 = kt * 16 + j * 8 + t * 2;
                float4 w0 = *(const float4*)&sW1[c0 * 4];
                float4 w1 = *(const float4*)&sW1[(c0 + 1) * 4];
                float bb0 = sB1[c0], bb1 = sB1[c0 + 1];
                float ya0 = fmaf(xa.x, w0.x, fmaf(xa.y, w0.y, fmaf(xa.z, w0.z, fmaf(xa.w, w0.w, bb0))));
                float ya1 = fmaf(xa.x, w1.x, fmaf(xa.y, w1.y, fmaf(xa.z, w1.z, fmaf(xa.w, w1.w, bb1))));
                float yb0 = fmaf(xb.x, w0.x, fmaf(xb.y, w0.y, fmaf(xb.z, w0.z, fmaf(xb.w, w0.w, bb0))));
                float yb1 = fmaf(xb.x, w1.x, fmaf(xb.y, w1.y, fmaf(xb.z, w1.z, fmaf(xb.w, w1.w, bb1))));
                h1A[kt][2 * j + 0] = pack_h2(fast_gelu(ya0), fast_gelu(ya1));
                h1A[kt][2 * j + 1] = pack_h2(fast_gelu(yb0), fast_gelu(yb1));
            }
    }

    // ================= layer 2: h1[16x128] @ W2 (4 N-chunks of 64) =================
    uint32_t h2A[16][4];
#pragma unroll
    for (int ci = 0; ci < 4; ++ci) {
        cp_wait<1>();
        __syncthreads();
        prefetch_chunk(ci + 2, S + (uint32_t)(((ci + 2) % 3) * 16384), tid);
        const uint32_t bb = S + (uint32_t)((ci % 3) * 16384);
#pragma unroll
        for (int j = 0; j < 4; ++j) {
            int ng = 4 * ci + j;
            int nb = ng * 16;
            // bias-seeded accumulators
            float b0 = sB2[nb + 2 * t], b1v = sB2[nb + 2 * t + 1];
            float b2v = sB2[nb + 8 + 2 * t], b3v = sB2[nb + 9 + 2 * t];
            float c[8] = {b0, b1v, b0, b1v, b2v, b3v, b2v, b3v};
            uint32_t bRow = bb + (uint32_t)((16 * j + wrow) * 256);
#pragma unroll
            for (int kt = 0; kt < 8; ++kt) {
                uint32_t B[4];
                ldmatrix_x4(B, bRow + (uint32_t)(((2 * kt + sel) ^ ri) << 4));
                mma16816(c + 0, h1A[kt], B[0], B[2]);
                mma16816(c + 4, h1A[kt], B[1], B[3]);
            }
            h2A[ng][0] = pack_h2(fast_gelu(c[0]), fast_gelu(c[1]));
            h2A[ng][1] = pack_h2(fast_gelu(c[2]), fast_gelu(c[3]));
            h2A[ng][2] = pack_h2(fast_gelu(c[4]), fast_gelu(c[5]));
            h2A[ng][3] = pack_h2(fast_gelu(c[6]), fast_gelu(c[7]));
        }
    }

    // ================= layer 3: h2[16x256] @ W3 (4 N-chunks of 32) =================
    uint32_t h3A[8][4];
#pragma unroll
    for (int ci = 4; ci < 8; ++ci) {
        cp_wait<1>();
        __syncthreads();
        prefetch_chunk(ci + 2, S + (uint32_t)(((ci + 2) % 3) * 16384), tid);
        const uint32_t bb = S + (uint32_t)((ci % 3) * 16384);
#pragma unroll
        for (int j = 0; j < 2; ++j) {
            int ng = 2 * (ci - 4) + j;
            int nb = ng * 16;
            float b0 = sB3[nb + 2 * t], b1v = sB3[nb + 2 * t + 1];
            float b2v = sB3[nb + 8 + 2 * t], b3v = sB3[nb + 9 + 2 * t];
            float c[8] = {b0, b1v, b0, b1v, b2v, b3v, b2v, b3v};
            uint32_t bRow = bb + (uint32_t)((16 * j + wrow) * 512);
#pragma unroll
            for (int kt = 0; kt < 16; ++kt) {
                uint32_t B[4];
                ldmatrix_x4(B, bRow + (uint32_t)(((2 * kt + sel) ^ ri) << 4));
                mma16816(c + 0, h2A[kt], B[0], B[2]);
                mma16816(c + 4, h2A[kt], B[1], B[3]);
            }
            h3A[ng][0] = pack_h2(fast_gelu(c[0]), fast_gelu(c[1]));
            h3A[ng][1] = pack_h2(fast_gelu(c[2]), fast_gelu(c[3]));
            h3A[ng][2] = pack_h2(fast_gelu(c[4]), fast_gelu(c[5]));
            h3A[ng][3] = pack_h2(fast_gelu(c[6]), fast_gelu(c[7]));
        }
    }

    // ---- epilogue row constants ----
    int pa = sPad[r0 + g], pb = sPad[r0 + g + 8];
    float ma = pa ? 0.0f : 1.0f;
    float mb = pb ? 0.0f : 1.0f;
    int ta = pa ? 0 : sTok[r0 + g];
    int tb = pb ? 0 : sTok[r0 + g + 8];
    const float* ea = emb + ta * 512;
    const float* eb = emb + tb * 512;
    float* outa = out + (size_t)(R0 + r0 + g) * 512;
    float* outb = out + (size_t)(R0 + r0 + g + 8) * 512;

    // ================= layer 4: h3[16x128] @ W4 (8 N-chunks of 64) + emb/pad =========
#pragma unroll
    for (int ci = 8; ci < 16; ++ci) {
        if (ci == 15) { cp_wait<0>(); } else { cp_wait<1>(); }
        __syncthreads();
        if (ci + 2 < 16) prefetch_chunk(ci + 2, S + (uint32_t)(((ci + 2) % 3) * 16384), tid);
        const uint32_t bb = S + (uint32_t)((ci % 3) * 16384);
#pragma unroll
        for (int j = 0; j < 4; ++j) {
            uint32_t bRow = bb + (uint32_t)((16 * j + wrow) * 256);
            float c[8] = {0, 0, 0, 0, 0, 0, 0, 0};
#pragma unroll
            for (int kt = 0; kt < 8; ++kt) {
                uint32_t B[4];
                ldmatrix_x4(B, bRow + (uint32_t)(((2 * kt + sel) ^ ri) << 4));
                mma16816(c + 0, h3A[kt], B[0], B[2]);
                mma16816(c + 4, h3A[kt], B[1], B[3]);
            }
            int cc0 = 64 * (ci - 8) + 16 * j + 2 * t;
            int cc1 = cc0 + 8;
            float2 e, o;
            e = *(const float2*)(ea + cc0);
            o.x = fmaf(ma, c[0], e.x);  o.y = fmaf(ma, c[1], e.y);
            *(float2*)(outa + cc0) = o;
            e = *(const float2*)(eb + cc0);
            o.x = fmaf(mb, c[2], e.x);  o.y = fmaf(mb, c[3], e.y);
            *(float2*)(outb + cc0) = o;
            e = *(const float2*)(ea + cc1);
            o.x = fmaf(ma, c[4], e.x);  o.y = fmaf(ma, c[5], e.y);
            *(float2*)(outa + cc1) = o;
            e = *(const float2*)(eb + cc1);
            o.x = fmaf(mb, c[6], e.x);  o.y = fmaf(mb, c[7], e.y);
            *(float2*)(outb + cc1) = o;
        }
    }
}

extern "C" void kernel_launch(void* const* d_in, const int* in_sizes, int n_in,
                              void* d_out, int out_size) {
    const float* joint_info  = (const float*)d_in[0];
    const int*   joint_token = (const int*)d_in[1];
    const float* emb         = (const float*)d_in[2];
    const float* W1          = (const float*)d_in[3];
    const float* b1          = (const float*)d_in[4];
    const float* W2          = (const float*)d_in[5];
    const float* b2          = (const float*)d_in[6];
    const float* W3          = (const float*)d_in[7];
    const float* b3          = (const float*)d_in[8];
    const float* W4          = (const float*)d_in[9];

    cvt_weights_kernel<<<256, 256>>>(W2, W3, W4);

    cudaFuncSetAttribute(embedder_kernel,
                         cudaFuncAttributeMaxDynamicSharedMemorySize, SMEM_BYTES);
    embedder_kernel<<<N_ROWS / TILE_M, NTHREADS, SMEM_BYTES>>>(
        joint_info, joint_token, emb, W1, b1, b2, b3, (float*)d_out);
}